// round 1
// baseline (speedup 1.0000x reference)
#include <cuda_runtime.h>
#include <math.h>

#define N_ATOMS 20000
#define N_EDGES 640000
#define FDIM    128
#define F3      (3 * FDIM)      // 384
#define N_RADIAL 20
#define CUTOFF  5.0f
#define PI_F    3.14159265358979323846f

// Scratch for per-node context x = Linear(silu(Linear(q))) : [N, 3F]
__device__ float g_x[(size_t)N_ATOMS * F3];

// ---------------------------------------------------------------------------
// Kernel 1: node MLP.  h = silu(q @ W1 + b1); x = h @ W2 + b2
// Block: 128 threads, handles 8 rows with register blocking.
// ---------------------------------------------------------------------------
__global__ __launch_bounds__(128)
void mlp_kernel(const float* __restrict__ q,
                const float* __restrict__ W1, const float* __restrict__ b1,
                const float* __restrict__ W2, const float* __restrict__ b2,
                float* __restrict__ x)
{
    __shared__ float qs[8][FDIM];
    __shared__ float hs[8][FDIM];

    const int f    = threadIdx.x;           // 0..127
    const int row0 = blockIdx.x * 8;        // 2500 blocks * 8 = 20000

    // cooperative load of 8 q rows
    #pragma unroll
    for (int t = 0; t < 8; t++) {
        int idx = t * FDIM + f;             // t-th chunk
        qs[idx >> 7][idx & 127] = q[(size_t)row0 * FDIM + idx];
    }
    __syncthreads();

    // stage 1: h[r][f] = silu(sum_k qs[r][k] * W1[k][f] + b1[f])
    float acc[8];
    {
        const float bb = b1[f];
        #pragma unroll
        for (int r = 0; r < 8; r++) acc[r] = bb;

        for (int k = 0; k < FDIM; k++) {
            const float w = W1[k * FDIM + f];
            #pragma unroll
            for (int r = 0; r < 8; r++) acc[r] += qs[r][k] * w;
        }
    }
    #pragma unroll
    for (int r = 0; r < 8; r++) {
        const float v = acc[r];
        hs[r][f] = v / (1.0f + __expf(-v));   // silu
    }
    __syncthreads();

    // stage 2: x[r][c] = sum_k hs[r][k] * W2[k][c] + b2[c], c in {f, f+128, f+256}
    float a0[8], a1[8], a2[8];
    {
        const float c0 = b2[f], c1 = b2[FDIM + f], c2 = b2[2 * FDIM + f];
        #pragma unroll
        for (int r = 0; r < 8; r++) { a0[r] = c0; a1[r] = c1; a2[r] = c2; }

        for (int k = 0; k < FDIM; k++) {
            const float w0 = W2[k * F3 + f];
            const float w1 = W2[k * F3 + FDIM + f];
            const float w2 = W2[k * F3 + 2 * FDIM + f];
            #pragma unroll
            for (int r = 0; r < 8; r++) {
                const float h = hs[r][k];
                a0[r] += h * w0;
                a1[r] += h * w1;
                a2[r] += h * w2;
            }
        }
    }
    #pragma unroll
    for (int r = 0; r < 8; r++) {
        const size_t base = (size_t)(row0 + r) * F3;
        x[base + f]            = a0[r];
        x[base + FDIM + f]     = a1[r];
        x[base + 2 * FDIM + f] = a2[r];
    }
}

// ---------------------------------------------------------------------------
// Kernel 2: per-edge filter + gather + scatter-add.
// Block: 256 threads = 2 edge-groups of 128 threads (one thread per channel).
// Grid-stride over edges.  Wf staged in shared.  Basis/env/dir computed by
// leader lanes only (avoids flooding MUFU).
// ---------------------------------------------------------------------------
__global__ __launch_bounds__(256)
void edge_kernel(const int*   __restrict__ edge_index,
                 const float* __restrict__ ew,
                 const float* __restrict__ mu,
                 const float* __restrict__ Wf,
                 const float* __restrict__ bf,
                 const float* __restrict__ x,
                 float* __restrict__ qout,
                 float* __restrict__ muout)
{
    __shared__ float sWf[N_RADIAL * F3];   // 30720 B
    __shared__ float sbasis[2][N_RADIAL];
    __shared__ float sdir[2][3];
    __shared__ float senv[2];

    const int g = threadIdx.x & 127;       // channel
    const int s = threadIdx.x >> 7;        // edge slot within block (0/1)

    // stage Wf in shared (reused for all edges this block processes)
    for (int t = threadIdx.x; t < N_RADIAL * F3; t += 256)
        sWf[t] = Wf[t];

    // loop-invariant bias per thread
    const float bq = bf[g];
    const float bR = bf[FDIM + g];
    const float bm = bf[2 * FDIM + g];

    __syncthreads();

    const int stride = gridDim.x * 2;
    for (int e = blockIdx.x * 2 + s; e < N_EDGES; e += stride) {
        const int i = edge_index[e];
        const int j = edge_index[N_EDGES + e];

        // leader lanes compute basis / env / direction
        if (g < 24) {
            const float ex = ew[3 * e + 0];
            const float ey = ew[3 * e + 1];
            const float ez = ew[3 * e + 2];
            const float d  = sqrtf(ex * ex + ey * ey + ez * ez);
            const float rd = 1.0f / d;
            if (g < N_RADIAL) {
                const float kg = (float)(g + 1) * (PI_F / CUTOFF);
                sbasis[s][g] = sinf(d * kg) * rd;
            } else if (g == 20) {
                const float env = 0.5f * (cosf(d * (PI_F / CUTOFF)) + 1.0f);
                senv[s] = (d < CUTOFF) ? env : 0.0f;
            } else if (g == 21) {
                sdir[s][0] = ex * rd;
            } else if (g == 22) {
                sdir[s][1] = ey * rd;
            } else { // g == 23
                sdir[s][2] = ez * rd;
            }
        }
        __syncthreads();

        // filter_Wij channels f, f+128, f+256
        float fq = bq, fR = bR, fm = bm;
        #pragma unroll
        for (int r = 0; r < N_RADIAL; r++) {
            const float b = sbasis[s][r];
            fq += b * sWf[r * F3 + g];
            fR += b * sWf[r * F3 + FDIM + g];
            fm += b * sWf[r * F3 + 2 * FDIM + g];
        }
        const float env = senv[s];
        fq *= env; fR *= env; fm *= env;

        // gather x[j] and mu[j]
        const float* xr = x  + (size_t)j * F3;
        const float* mr = mu + (size_t)j * F3;
        const float dq = fq * xr[g];
        const float dR = fR * xr[FDIM + g];
        const float dm = fm * xr[2 * FDIM + g];
        const float m0 = mr[g];
        const float m1 = mr[FDIM + g];
        const float m2 = mr[2 * FDIM + g];

        const float d0 = sdir[s][0];
        const float d1 = sdir[s][1];
        const float d2 = sdir[s][2];

        atomicAdd(qout + (size_t)i * FDIM + g, dq);
        float* mo = muout + (size_t)i * F3;
        atomicAdd(mo + g,            dR * d0 + dm * m0);
        atomicAdd(mo + FDIM + g,     dR * d1 + dm * m1);
        atomicAdd(mo + 2 * FDIM + g, dR * d2 + dm * m2);

        __syncthreads();   // protect shared per-edge data before next iter
    }
}

// ---------------------------------------------------------------------------
extern "C" void kernel_launch(void* const* d_in, const int* in_sizes, int n_in,
                              void* d_out, int out_size)
{
    const float* q   = (const float*)d_in[0];
    const float* mu  = (const float*)d_in[1];
    const int*   ei  = (const int*)  d_in[2];
    const float* ew  = (const float*)d_in[3];
    const float* W1  = (const float*)d_in[4];
    const float* b1  = (const float*)d_in[5];
    const float* W2  = (const float*)d_in[6];
    const float* b2  = (const float*)d_in[7];
    const float* Wf  = (const float*)d_in[8];
    const float* bf  = (const float*)d_in[9];

    float* out   = (float*)d_out;
    float* qout  = out;                                   // [N, F]
    float* muout = out + (size_t)N_ATOMS * FDIM;          // [N, 3, F]

    // seed outputs with q and mu (atomics accumulate the updates)
    cudaMemcpyAsync(qout,  q,  (size_t)N_ATOMS * FDIM * sizeof(float),
                    cudaMemcpyDeviceToDevice, 0);
    cudaMemcpyAsync(muout, mu, (size_t)N_ATOMS * F3 * sizeof(float),
                    cudaMemcpyDeviceToDevice, 0);

    // node MLP -> g_x
    mlp_kernel<<<N_ATOMS / 8, 128>>>(q, W1, b1, W2, b2, g_x);

    // edges: filter + gather + scatter-add
    edge_kernel<<<1480, 256>>>(ei, ew, mu, Wf, bf, g_x, qout, muout);
}

// round 2
// speedup vs baseline: 5.4215x; 5.4215x over previous
#include <cuda_runtime.h>
#include <math.h>

#define N_ATOMS 20000
#define N_EDGES 640000
#define FDIM    128
#define F3      (3 * FDIM)      // 384
#define N_RADIAL 20
#define CUTOFF  5.0f
#define PI_F    3.14159265358979323846f

typedef unsigned long long u64;

// ---------------- scratch (static device globals; no runtime allocs) -------
__device__ float g_x[(size_t)N_ATOMS * F3];                 // node context [N,3F]
__device__ float g_filter[(size_t)N_EDGES * F3];            // per-edge filter [E,3F]
__device__ float g_dir[(size_t)N_EDGES * 4];                // per-edge direction
__device__ int   g_count[N_ATOMS];
__device__ int   g_off[N_ATOMS + 1];
__device__ int   g_cursor[N_ATOMS];
__device__ int   g_eid[N_EDGES];

// ---------------- f32x2 packed helpers -------------------------------------
__device__ __forceinline__ u64 pack2(float x, float y) {
    u64 r; asm("mov.b64 %0, {%1,%2};" : "=l"(r) : "f"(x), "f"(y)); return r;
}
__device__ __forceinline__ void fma2(u64& d, u64 a, u64 b) {
    asm("fma.rn.f32x2 %0, %1, %2, %0;" : "+l"(d) : "l"(a), "l"(b));
}

// ---------------------------------------------------------------------------
// Kernel 1: node MLP.  h = silu(q @ W1 + b1); x = h @ W2 + b2
// ---------------------------------------------------------------------------
__global__ __launch_bounds__(128)
void mlp_kernel(const float* __restrict__ q,
                const float* __restrict__ W1, const float* __restrict__ b1,
                const float* __restrict__ W2, const float* __restrict__ b2,
                float* __restrict__ x)
{
    __shared__ float qs[8][FDIM];
    __shared__ float hs[8][FDIM];

    const int f    = threadIdx.x;
    const int row0 = blockIdx.x * 8;

    #pragma unroll
    for (int t = 0; t < 8; t++) {
        int idx = t * FDIM + f;
        qs[idx >> 7][idx & 127] = q[(size_t)row0 * FDIM + idx];
    }
    __syncthreads();

    float acc[8];
    {
        const float bb = b1[f];
        #pragma unroll
        for (int r = 0; r < 8; r++) acc[r] = bb;
        for (int k = 0; k < FDIM; k++) {
            const float w = W1[k * FDIM + f];
            #pragma unroll
            for (int r = 0; r < 8; r++) acc[r] += qs[r][k] * w;
        }
    }
    #pragma unroll
    for (int r = 0; r < 8; r++) {
        const float v = acc[r];
        hs[r][f] = v / (1.0f + __expf(-v));
    }
    __syncthreads();

    float a0[8], a1[8], a2[8];
    {
        const float c0 = b2[f], c1 = b2[FDIM + f], c2 = b2[2 * FDIM + f];
        #pragma unroll
        for (int r = 0; r < 8; r++) { a0[r] = c0; a1[r] = c1; a2[r] = c2; }
        for (int k = 0; k < FDIM; k++) {
            const float w0 = W2[k * F3 + f];
            const float w1 = W2[k * F3 + FDIM + f];
            const float w2 = W2[k * F3 + 2 * FDIM + f];
            #pragma unroll
            for (int r = 0; r < 8; r++) {
                const float h = hs[r][k];
                a0[r] += h * w0; a1[r] += h * w1; a2[r] += h * w2;
            }
        }
    }
    #pragma unroll
    for (int r = 0; r < 8; r++) {
        const size_t base = (size_t)(row0 + r) * F3;
        x[base + f]            = a0[r];
        x[base + FDIM + f]     = a1[r];
        x[base + 2 * FDIM + f] = a2[r];
    }
}

// ---------------------------------------------------------------------------
// CSR construction: zero -> histogram -> scan -> scatter
// ---------------------------------------------------------------------------
__global__ void zero_counts()
{
    int i = blockIdx.x * blockDim.x + threadIdx.x;
    if (i < N_ATOMS) g_count[i] = 0;
}

__global__ void hist_kernel(const int* __restrict__ edge_index)
{
    int e = blockIdx.x * blockDim.x + threadIdx.x;
    if (e < N_EDGES) atomicAdd(&g_count[edge_index[e]], 1);
}

__global__ __launch_bounds__(1024)
void scan_kernel()
{
    __shared__ int sh[1024];
    const int tid = threadIdx.x;
    int carry = 0;
    const int nchunks = (N_ATOMS + 1023) / 1024;
    for (int c = 0; c < nchunks; c++) {
        int idx = c * 1024 + tid;
        int v = (idx < N_ATOMS) ? g_count[idx] : 0;
        sh[tid] = v;
        __syncthreads();
        #pragma unroll
        for (int ofs = 1; ofs < 1024; ofs <<= 1) {
            int t = (tid >= ofs) ? sh[tid - ofs] : 0;
            __syncthreads();
            sh[tid] += t;
            __syncthreads();
        }
        int excl = carry + sh[tid] - v;
        if (idx < N_ATOMS) { g_off[idx] = excl; g_cursor[idx] = excl; }
        int tot = sh[1023];
        __syncthreads();
        carry += tot;
    }
    if (tid == 0) g_off[N_ATOMS] = carry;
}

__global__ void scatter_kernel(const int* __restrict__ edge_index)
{
    int e = blockIdx.x * blockDim.x + threadIdx.x;
    if (e < N_EDGES) {
        int pos = atomicAdd(&g_cursor[edge_index[e]], 1);
        g_eid[pos] = e;
    }
}

// ---------------------------------------------------------------------------
// Kernel 2: per-edge filter.  One warp per edge.  Wf staged in shared.
// filter = (basis @ Wf + bf) * env, where basis already includes 1/d; env
// folded into both terms.  Also writes unit direction.
// ---------------------------------------------------------------------------
__global__ __launch_bounds__(256)
void filter_kernel(const float* __restrict__ ew,
                   const float* __restrict__ Wf,
                   const float* __restrict__ bf,
                   float* __restrict__ filt,
                   float* __restrict__ dir)
{
    __shared__ float sWf[N_RADIAL * F3];   // 30720 B
    __shared__ float sbf[F3];

    for (int t = threadIdx.x; t < N_RADIAL * F3; t += 256) sWf[t] = Wf[t];
    for (int t = threadIdx.x; t < F3; t += 256)            sbf[t] = bf[t];
    __syncthreads();

    const int warp = threadIdx.x >> 5;
    const int lane = threadIdx.x & 31;
    const int estride = gridDim.x * 8;

    for (int e = blockIdx.x * 8 + warp; e < N_EDGES; e += estride) {
        const float ex = ew[3 * e + 0];
        const float ey = ew[3 * e + 1];
        const float ez = ew[3 * e + 2];
        const float dd = fmaf(ex, ex, fmaf(ey, ey, ez * ez));
        const float rd = rsqrtf(dd);
        const float d  = dd * rd;
        float env = 0.5f * (cosf(d * (PI_F / CUTOFF)) + 1.0f);
        env = (d < CUTOFF) ? env : 0.0f;

        // lane r computes basis_r * env (lanes >= 20 unused)
        const float bs = sinf(d * (float)(lane + 1) * (PI_F / CUTOFF)) * rd * env;

        // accumulators: 12 channels/lane as 6 packed f32x2; c = 64*k + 2*lane
        u64 acc[6];
        #pragma unroll
        for (int k = 0; k < 6; k++) {
            const int c = 64 * k + 2 * lane;
            acc[k] = pack2(sbf[c] * env, sbf[c + 1] * env);
        }
        #pragma unroll
        for (int r = 0; r < N_RADIAL; r++) {
            const float b = __shfl_sync(0xffffffffu, bs, r);
            const u64 bb = pack2(b, b);
            #pragma unroll
            for (int k = 0; k < 6; k++) {
                const u64 w = *(const u64*)&sWf[r * F3 + 64 * k + 2 * lane];
                fma2(acc[k], bb, w);
            }
        }
        float* fo = filt + (size_t)e * F3;
        #pragma unroll
        for (int k = 0; k < 6; k++)
            *(u64*)&fo[64 * k + 2 * lane] = acc[k];

        if (lane < 3)
            dir[(size_t)e * 4 + lane] = (lane == 0 ? ex : (lane == 1 ? ey : ez)) * rd;
    }
}

// ---------------------------------------------------------------------------
// Kernel 3: node accumulation.  One block per node, thread = channel.
// Pulls all incident edges; no atomics; writes final output.
// ---------------------------------------------------------------------------
__global__ __launch_bounds__(128)
void node_kernel(const int*   __restrict__ edge_index,
                 const float* __restrict__ q,
                 const float* __restrict__ mu,
                 float* __restrict__ qout,
                 float* __restrict__ muout)
{
    const int i = blockIdx.x;
    const int c = threadIdx.x;
    const int beg = g_off[i];
    const int end = g_off[i + 1];

    float aq = 0.0f, a0 = 0.0f, a1 = 0.0f, a2 = 0.0f;

    #pragma unroll 2
    for (int t = beg; t < end; t++) {
        const int eid = g_eid[t];
        const int j   = edge_index[N_EDGES + eid];
        const float d0 = g_dir[(size_t)eid * 4 + 0];
        const float d1 = g_dir[(size_t)eid * 4 + 1];
        const float d2 = g_dir[(size_t)eid * 4 + 2];

        const float* fr = g_filter + (size_t)eid * F3;
        const float fq = __ldcs(fr + c);
        const float fR = __ldcs(fr + FDIM + c);
        const float fm = __ldcs(fr + 2 * FDIM + c);

        const float* xr = g_x + (size_t)j * F3;
        const float dq = fq * xr[c];
        const float dR = fR * xr[FDIM + c];
        const float dm = fm * xr[2 * FDIM + c];

        const float* mr = mu + (size_t)j * F3;
        aq += dq;
        a0 += dR * d0 + dm * mr[c];
        a1 += dR * d1 + dm * mr[FDIM + c];
        a2 += dR * d2 + dm * mr[2 * FDIM + c];
    }

    qout[(size_t)i * FDIM + c] = q[(size_t)i * FDIM + c] + aq;
    float* mo = muout + (size_t)i * F3;
    const float* mi = mu + (size_t)i * F3;
    mo[c]            = mi[c]            + a0;
    mo[FDIM + c]     = mi[FDIM + c]     + a1;
    mo[2 * FDIM + c] = mi[2 * FDIM + c] + a2;
}

// ---------------------------------------------------------------------------
extern "C" void kernel_launch(void* const* d_in, const int* in_sizes, int n_in,
                              void* d_out, int out_size)
{
    const float* q   = (const float*)d_in[0];
    const float* mu  = (const float*)d_in[1];
    const int*   ei  = (const int*)  d_in[2];
    const float* ew  = (const float*)d_in[3];
    const float* W1  = (const float*)d_in[4];
    const float* b1  = (const float*)d_in[5];
    const float* W2  = (const float*)d_in[6];
    const float* b2  = (const float*)d_in[7];
    const float* Wf  = (const float*)d_in[8];
    const float* bf  = (const float*)d_in[9];

    float* out   = (float*)d_out;
    float* qout  = out;                                   // [N, F]
    float* muout = out + (size_t)N_ATOMS * FDIM;          // [N, 3, F]

    float* fx;   cudaGetSymbolAddress((void**)&fx,   g_x);
    float* ffl;  cudaGetSymbolAddress((void**)&ffl,  g_filter);
    float* fdir; cudaGetSymbolAddress((void**)&fdir, g_dir);

    // CSR build (order within a node nondeterministic; fp-sum order only)
    zero_counts<<<(N_ATOMS + 255) / 256, 256>>>();
    hist_kernel<<<N_EDGES / 256, 256>>>(ei);
    scan_kernel<<<1, 1024>>>();
    scatter_kernel<<<N_EDGES / 256, 256>>>(ei);

    // node MLP -> g_x
    mlp_kernel<<<N_ATOMS / 8, 128>>>(q, W1, b1, W2, b2, fx);

    // per-edge filter + direction
    filter_kernel<<<2048, 256>>>(ew, Wf, bf, ffl, fdir);

    // pull-mode accumulation, writes final outputs
    node_kernel<<<N_ATOMS, 128>>>(ei, q, mu, qout, muout);
}

// round 3
// speedup vs baseline: 7.8700x; 1.4516x over previous
#include <cuda_runtime.h>
#include <math.h>

#define N_ATOMS 20000
#define N_EDGES 640000
#define FDIM    128
#define F3      (3 * FDIM)      // 384
#define N_RADIAL 20
#define CUTOFF  5.0f
#define PI_F    3.14159265358979323846f

typedef unsigned long long u64;

// ---------------- scratch (static device globals; no runtime allocs) -------
__device__ float g_x[(size_t)N_ATOMS * F3];        // node context [N,3F]
__device__ float g_edata[(size_t)N_EDGES * 24];    // per edge: d0,d1,d2,env,b0..b19 (b has rd*env folded)
__device__ int   g_count[N_ATOMS];
__device__ int   g_off[N_ATOMS + 1];
__device__ int   g_cursor[N_ATOMS];
__device__ int2  g_edge[N_EDGES];                  // (eid, j) grouped by dest i

// ---------------- f32x2 packed helpers -------------------------------------
__device__ __forceinline__ u64 pack2(float x, float y) {
    u64 r; asm("mov.b64 %0, {%1,%2};" : "=l"(r) : "f"(x), "f"(y)); return r;
}
__device__ __forceinline__ void unpack2(u64 v, float& x, float& y) {
    asm("mov.b64 {%0,%1}, %2;" : "=f"(x), "=f"(y) : "l"(v));
}
__device__ __forceinline__ void fma2(u64& d, u64 a, u64 b) {
    asm("fma.rn.f32x2 %0, %1, %2, %0;" : "+l"(d) : "l"(a), "l"(b));
}

// ---------------------------------------------------------------------------
// Kernel 1: node MLP.  h = silu(q @ W1 + b1); x = h @ W2 + b2
// ---------------------------------------------------------------------------
__global__ __launch_bounds__(128)
void mlp_kernel(const float* __restrict__ q,
                const float* __restrict__ W1, const float* __restrict__ b1,
                const float* __restrict__ W2, const float* __restrict__ b2,
                float* __restrict__ x)
{
    __shared__ float qs[8][FDIM];
    __shared__ float hs[8][FDIM];

    const int f    = threadIdx.x;
    const int row0 = blockIdx.x * 8;

    #pragma unroll
    for (int t = 0; t < 8; t++) {
        int idx = t * FDIM + f;
        qs[idx >> 7][idx & 127] = q[(size_t)row0 * FDIM + idx];
    }
    __syncthreads();

    float acc[8];
    {
        const float bb = b1[f];
        #pragma unroll
        for (int r = 0; r < 8; r++) acc[r] = bb;
        for (int k = 0; k < FDIM; k++) {
            const float w = W1[k * FDIM + f];
            #pragma unroll
            for (int r = 0; r < 8; r++) acc[r] += qs[r][k] * w;
        }
    }
    #pragma unroll
    for (int r = 0; r < 8; r++) {
        const float v = acc[r];
        hs[r][f] = v / (1.0f + __expf(-v));
    }
    __syncthreads();

    float a0[8], a1[8], a2[8];
    {
        const float c0 = b2[f], c1 = b2[FDIM + f], c2 = b2[2 * FDIM + f];
        #pragma unroll
        for (int r = 0; r < 8; r++) { a0[r] = c0; a1[r] = c1; a2[r] = c2; }
        for (int k = 0; k < FDIM; k++) {
            const float w0 = W2[k * F3 + f];
            const float w1 = W2[k * F3 + FDIM + f];
            const float w2 = W2[k * F3 + 2 * FDIM + f];
            #pragma unroll
            for (int r = 0; r < 8; r++) {
                const float h = hs[r][k];
                a0[r] += h * w0; a1[r] += h * w1; a2[r] += h * w2;
            }
        }
    }
    #pragma unroll
    for (int r = 0; r < 8; r++) {
        const size_t base = (size_t)(row0 + r) * F3;
        x[base + f]            = a0[r];
        x[base + FDIM + f]     = a1[r];
        x[base + 2 * FDIM + f] = a2[r];
    }
}

// ---------------------------------------------------------------------------
// CSR construction: zero -> histogram -> scan -> scatter (stores (eid, j))
// ---------------------------------------------------------------------------
__global__ void zero_counts()
{
    int i = blockIdx.x * blockDim.x + threadIdx.x;
    if (i < N_ATOMS) g_count[i] = 0;
}

__global__ void hist_kernel(const int* __restrict__ edge_index)
{
    int e = blockIdx.x * blockDim.x + threadIdx.x;
    if (e < N_EDGES) atomicAdd(&g_count[edge_index[e]], 1);
}

// single-block scan via warp shuffles (2 barriers per 1024-chunk)
__global__ __launch_bounds__(1024)
void scan_kernel()
{
    __shared__ int warp_sums[32];
    __shared__ int chunk_carry;
    const int tid  = threadIdx.x;
    const int lane = tid & 31;
    const int wid  = tid >> 5;
    if (tid == 0) chunk_carry = 0;
    __syncthreads();

    const int nchunks = (N_ATOMS + 1023) / 1024;
    for (int c = 0; c < nchunks; c++) {
        int idx = c * 1024 + tid;
        int v = (idx < N_ATOMS) ? g_count[idx] : 0;

        // inclusive warp scan
        int s = v;
        #pragma unroll
        for (int o = 1; o < 32; o <<= 1) {
            int t = __shfl_up_sync(0xffffffffu, s, o);
            if (lane >= o) s += t;
        }
        if (lane == 31) warp_sums[wid] = s;
        __syncthreads();
        if (wid == 0) {
            int ws = warp_sums[lane];
            #pragma unroll
            for (int o = 1; o < 32; o <<= 1) {
                int t = __shfl_up_sync(0xffffffffu, ws, o);
                if (lane >= o) ws += t;
            }
            warp_sums[lane] = ws;
        }
        __syncthreads();
        int warp_off = (wid > 0) ? warp_sums[wid - 1] : 0;
        int excl = chunk_carry + warp_off + s - v;
        if (idx < N_ATOMS) { g_off[idx] = excl; g_cursor[idx] = excl; }
        __syncthreads();
        if (tid == 1023) chunk_carry += warp_off + s;
    }
    __syncthreads();
    if (tid == 0) g_off[N_ATOMS] = chunk_carry;
}

__global__ void scatter_kernel(const int* __restrict__ edge_index)
{
    int e = blockIdx.x * blockDim.x + threadIdx.x;
    if (e < N_EDGES) {
        int pos = atomicAdd(&g_cursor[edge_index[e]], 1);
        g_edge[pos] = make_int2(e, edge_index[N_EDGES + e]);
    }
}

// ---------------------------------------------------------------------------
// Kernel 2: per-edge geometry: direction, envelope, basis (rd*env folded).
// One thread per edge; sin(n x) via Chebyshev recurrence (1 sincos per edge).
// Staged through shared for coalesced 96B/edge writes.
// ---------------------------------------------------------------------------
__global__ __launch_bounds__(256)
void edata_kernel(const float* __restrict__ ew, float* __restrict__ edata)
{
    __shared__ float sh[256 * 25];   // 25-stride to dodge bank conflicts
    const int tid = threadIdx.x;
    const int e0  = blockIdx.x * 256;
    const int e   = e0 + tid;

    const float ex = ew[3 * e + 0];
    const float ey = ew[3 * e + 1];
    const float ez = ew[3 * e + 2];
    const float dd = fmaf(ex, ex, fmaf(ey, ey, ez * ez));
    const float rd = rsqrtf(dd);
    const float d  = dd * rd;

    const float xx = d * (PI_F / CUTOFF);
    float s1, c1;
    __sincosf(xx, &s1, &c1);
    float env = 0.5f * (c1 + 1.0f);
    env = (d < CUTOFF) ? env : 0.0f;

    float* row = &sh[tid * 25];
    row[0] = ex * rd;
    row[1] = ey * rd;
    row[2] = ez * rd;
    row[3] = env;

    const float re = rd * env;
    const float two_c = 2.0f * c1;
    float sm1 = 0.0f, sn = s1;
    #pragma unroll
    for (int n = 0; n < N_RADIAL; n++) {
        row[4 + n] = sn * re;
        const float nx = two_c * sn - sm1;
        sm1 = sn; sn = nx;
    }
    __syncthreads();

    // coalesced write-out: 256 edges * 24 floats
    float* dst = edata + (size_t)e0 * 24;
    for (int idx = tid; idx < 256 * 24; idx += 256) {
        int le = idx / 24, k = idx - le * 24;
        dst[idx] = sh[le * 25 + k];
    }
}

// ---------------------------------------------------------------------------
// Kernel 3 (fused): node accumulation with in-register Wf matvec.
// Block = 128 threads = one node; thread c owns channels c, c+128, c+256.
// Per edge: 1 lane-load + 24 shfl for edata; 20 fma2 + 20 fma matvec;
// gather x[j], mu[j]; register accumulate; no atomics, no barriers.
// ---------------------------------------------------------------------------
__global__ __launch_bounds__(128)
void node_kernel(const float* __restrict__ q,
                 const float* __restrict__ mu,
                 const float* __restrict__ Wf,
                 const float* __restrict__ bf,
                 const float* __restrict__ edata,
                 float* __restrict__ qout,
                 float* __restrict__ muout)
{
    const int i    = blockIdx.x;
    const int c    = threadIdx.x;
    const int lane = c & 31;

    // Wf slices into registers (L1-resident broadcast across blocks)
    u64   wqr[N_RADIAL];
    float wm[N_RADIAL];
    #pragma unroll
    for (int r = 0; r < N_RADIAL; r++) {
        wqr[r] = pack2(Wf[r * F3 + c], Wf[r * F3 + FDIM + c]);
        wm[r]  = Wf[r * F3 + 2 * FDIM + c];
    }
    const float bq = bf[c], bR = bf[FDIM + c], bm = bf[2 * FDIM + c];

    const int beg = g_off[i];
    const int end = g_off[i + 1];

    float aq = 0.0f, a0 = 0.0f, a1 = 0.0f, a2 = 0.0f;

    for (int t = beg; t < end; t++) {
        const int2 ej = g_edge[t];
        const int  e  = ej.x;
        const int  j  = ej.y;

        // one coalesced lane-load of the 24-float edge record, then shfl
        const float* er = edata + (size_t)e * 24;
        const float v = (lane < 24) ? er[lane] : 0.0f;
        const float d0  = __shfl_sync(0xffffffffu, v, 0);
        const float d1  = __shfl_sync(0xffffffffu, v, 1);
        const float d2  = __shfl_sync(0xffffffffu, v, 2);
        const float env = __shfl_sync(0xffffffffu, v, 3);

        // filter matvec, Wf in registers, (fq,fR) packed
        u64   fqr = pack2(bq * env, bR * env);
        float fm  = bm * env;
        #pragma unroll
        for (int r = 0; r < N_RADIAL; r++) {
            const float b = __shfl_sync(0xffffffffu, v, 4 + r);
            fma2(fqr, pack2(b, b), wqr[r]);
            fm = fmaf(b, wm[r], fm);
        }
        float fq, fR; unpack2(fqr, fq, fR);

        const float* xr = g_x + (size_t)j * F3;
        const float dq = fq * xr[c];
        const float dR = fR * xr[FDIM + c];
        const float dm = fm * xr[2 * FDIM + c];

        const float* mr = mu + (size_t)j * F3;
        aq += dq;
        a0 = fmaf(dR, d0, fmaf(dm, mr[c],            a0));
        a1 = fmaf(dR, d1, fmaf(dm, mr[FDIM + c],     a1));
        a2 = fmaf(dR, d2, fmaf(dm, mr[2 * FDIM + c], a2));
    }

    qout[(size_t)i * FDIM + c] = q[(size_t)i * FDIM + c] + aq;
    float* mo = muout + (size_t)i * F3;
    const float* mi = mu + (size_t)i * F3;
    mo[c]            = mi[c]            + a0;
    mo[FDIM + c]     = mi[FDIM + c]     + a1;
    mo[2 * FDIM + c] = mi[2 * FDIM + c] + a2;
}

// ---------------------------------------------------------------------------
extern "C" void kernel_launch(void* const* d_in, const int* in_sizes, int n_in,
                              void* d_out, int out_size)
{
    const float* q   = (const float*)d_in[0];
    const float* mu  = (const float*)d_in[1];
    const int*   ei  = (const int*)  d_in[2];
    const float* ew  = (const float*)d_in[3];
    const float* W1  = (const float*)d_in[4];
    const float* b1  = (const float*)d_in[5];
    const float* W2  = (const float*)d_in[6];
    const float* b2  = (const float*)d_in[7];
    const float* Wf  = (const float*)d_in[8];
    const float* bf  = (const float*)d_in[9];

    float* out   = (float*)d_out;
    float* qout  = out;                                   // [N, F]
    float* muout = out + (size_t)N_ATOMS * FDIM;          // [N, 3, F]

    float* fx; cudaGetSymbolAddress((void**)&fx, g_x);
    float* fe; cudaGetSymbolAddress((void**)&fe, g_edata);

    // CSR build
    zero_counts<<<(N_ATOMS + 255) / 256, 256>>>();
    hist_kernel<<<N_EDGES / 256, 256>>>(ei);
    scan_kernel<<<1, 1024>>>();
    scatter_kernel<<<N_EDGES / 256, 256>>>(ei);

    // node MLP -> g_x
    mlp_kernel<<<N_ATOMS / 8, 128>>>(q, W1, b1, W2, b2, fx);

    // per-edge geometry record
    edata_kernel<<<N_EDGES / 256, 256>>>(ew, fe);

    // fused filter + pull accumulation, writes final outputs
    node_kernel<<<N_ATOMS, 128>>>(q, mu, Wf, bf, fe, qout, muout);
}

// round 4
// speedup vs baseline: 10.7750x; 1.3691x over previous
#include <cuda_runtime.h>
#include <math.h>

#define N_ATOMS 20000
#define N_EDGES 640000
#define FDIM    128
#define F3      (3 * FDIM)      // 384
#define N_RADIAL 20
#define CUTOFF  5.0f
#define PI_F    3.14159265358979323846f

typedef unsigned long long u64;

// ---------------- scratch (static device globals; no runtime allocs) -------
__device__ float g_x[(size_t)N_ATOMS * F3];   // node context [N,3F]
__device__ int   g_count[N_ATOMS];
__device__ int   g_off[N_ATOMS + 1];
__device__ int   g_cursor[N_ATOMS];
__device__ int   g_perm[N_EDGES];             // slot -> original edge id
__device__ int   g_j[N_EDGES];                // slot -> source node j

// ---------------- f32x2 packed helpers -------------------------------------
__device__ __forceinline__ u64 pack2(float x, float y) {
    u64 r; asm("mov.b64 %0, {%1,%2};" : "=l"(r) : "f"(x), "f"(y)); return r;
}
__device__ __forceinline__ void unpack2(u64 v, float& x, float& y) {
    asm("mov.b64 {%0,%1}, %2;" : "=f"(x), "=f"(y) : "l"(v));
}
__device__ __forceinline__ void fma2(u64& d, u64 a, u64 b) {
    asm("fma.rn.f32x2 %0, %1, %2, %0;" : "+l"(d) : "l"(a), "l"(b));
}

// ---------------------------------------------------------------------------
// Kernel 1: node MLP.  32 rows per block, 256 threads (2 halves x 16 rows).
// Weight rows broadcast via L1; L2 weight traffic = 625 blocks * 1MB.
// ---------------------------------------------------------------------------
__global__ __launch_bounds__(256)
void mlp_kernel(const float* __restrict__ q,
                const float* __restrict__ W1, const float* __restrict__ b1,
                const float* __restrict__ W2, const float* __restrict__ b2,
                float* __restrict__ x)
{
    __shared__ float qs[32][FDIM];   // 16 KB
    __shared__ float hs[32][FDIM];   // 16 KB

    const int f    = threadIdx.x & 127;
    const int half = threadIdx.x >> 7;     // 0/1 -> rows half*16 .. half*16+15
    const int row0 = blockIdx.x * 32;

    for (int idx = threadIdx.x; idx < 32 * FDIM; idx += 256)
        qs[idx >> 7][idx & 127] = q[(size_t)row0 * FDIM + idx];
    __syncthreads();

    // stage 1
    {
        float acc[16];
        const float bb = b1[f];
        #pragma unroll
        for (int r = 0; r < 16; r++) acc[r] = bb;
        for (int k = 0; k < FDIM; k++) {
            const float w = W1[k * FDIM + f];
            #pragma unroll
            for (int r = 0; r < 16; r++) acc[r] += qs[half * 16 + r][k] * w;
        }
        #pragma unroll
        for (int r = 0; r < 16; r++) {
            const float v = acc[r];
            hs[half * 16 + r][f] = v / (1.0f + __expf(-v));
        }
    }
    __syncthreads();

    // stage 2
    {
        float a0[16], a1[16], a2[16];
        const float c0 = b2[f], c1 = b2[FDIM + f], c2 = b2[2 * FDIM + f];
        #pragma unroll
        for (int r = 0; r < 16; r++) { a0[r] = c0; a1[r] = c1; a2[r] = c2; }
        for (int k = 0; k < FDIM; k++) {
            const float w0 = W2[k * F3 + f];
            const float w1 = W2[k * F3 + FDIM + f];
            const float w2 = W2[k * F3 + 2 * FDIM + f];
            #pragma unroll
            for (int r = 0; r < 16; r++) {
                const float h = hs[half * 16 + r][k];
                a0[r] += h * w0; a1[r] += h * w1; a2[r] += h * w2;
            }
        }
        #pragma unroll
        for (int r = 0; r < 16; r++) {
            const size_t base = (size_t)(row0 + half * 16 + r) * F3;
            x[base + f]            = a0[r];
            x[base + FDIM + f]     = a1[r];
            x[base + 2 * FDIM + f] = a2[r];
        }
    }
}

// ---------------------------------------------------------------------------
// CSR construction: zero -> histogram -> scan -> scatter (perm + j)
// ---------------------------------------------------------------------------
__global__ void zero_counts()
{
    int i = blockIdx.x * blockDim.x + threadIdx.x;
    if (i < N_ATOMS) g_count[i] = 0;
}

__global__ void hist_kernel(const int* __restrict__ edge_index)
{
    int e = blockIdx.x * blockDim.x + threadIdx.x;
    if (e < N_EDGES) atomicAdd(&g_count[edge_index[e]], 1);
}

__global__ __launch_bounds__(1024)
void scan_kernel()
{
    __shared__ int warp_sums[32];
    __shared__ int chunk_carry;
    const int tid  = threadIdx.x;
    const int lane = tid & 31;
    const int wid  = tid >> 5;
    if (tid == 0) chunk_carry = 0;
    __syncthreads();

    const int nchunks = (N_ATOMS + 1023) / 1024;
    for (int c = 0; c < nchunks; c++) {
        int idx = c * 1024 + tid;
        int v = (idx < N_ATOMS) ? g_count[idx] : 0;
        int s = v;
        #pragma unroll
        for (int o = 1; o < 32; o <<= 1) {
            int t = __shfl_up_sync(0xffffffffu, s, o);
            if (lane >= o) s += t;
        }
        if (lane == 31) warp_sums[wid] = s;
        __syncthreads();
        if (wid == 0) {
            int ws = warp_sums[lane];
            #pragma unroll
            for (int o = 1; o < 32; o <<= 1) {
                int t = __shfl_up_sync(0xffffffffu, ws, o);
                if (lane >= o) ws += t;
            }
            warp_sums[lane] = ws;
        }
        __syncthreads();
        int warp_off = (wid > 0) ? warp_sums[wid - 1] : 0;
        int excl = chunk_carry + warp_off + s - v;
        if (idx < N_ATOMS) { g_off[idx] = excl; g_cursor[idx] = excl; }
        __syncthreads();
        if (tid == 1023) chunk_carry += warp_off + s;
    }
    __syncthreads();
    if (tid == 0) g_off[N_ATOMS] = chunk_carry;
}

__global__ void scatter_kernel(const int* __restrict__ edge_index)
{
    int e = blockIdx.x * blockDim.x + threadIdx.x;
    if (e < N_EDGES) {
        int pos = atomicAdd(&g_cursor[edge_index[e]], 1);
        g_perm[pos] = e;
        g_j[pos]    = edge_index[N_EDGES + e];
    }
}

// ---------------------------------------------------------------------------
// Kernel 2 (fused): per-node accumulation.
// Block = one node, 128 threads (thread c owns channels c, c+128, c+256).
// Stages chunks of 64 edges into shared: one thread per edge computes the
// geometry record (dir, env, 20 duplicated basis pairs) in-place; the inner
// loop then runs entirely on broadcast LDS + registers + 6 L2 gathers/edge.
// No atomics; final outputs written directly.
// ---------------------------------------------------------------------------
#define CHUNK 64
#define RECW  46    // 4 scalars + 20 duplicated pairs (44), padded to even 46

__global__ __launch_bounds__(128)
void node_kernel(const float* __restrict__ q,
                 const float* __restrict__ mu,
                 const float* __restrict__ ew,
                 const float* __restrict__ Wf,
                 const float* __restrict__ bf,
                 float* __restrict__ qout,
                 float* __restrict__ muout)
{
    __shared__ float srec[CHUNK][RECW];   // 11776 B
    __shared__ int   sj[CHUNK];

    const int i = blockIdx.x;
    const int c = threadIdx.x;

    // Wf slices in registers (same 60 KB broadcast to every block -> L1 hot)
    u64   wqr[N_RADIAL];
    float wm[N_RADIAL];
    #pragma unroll
    for (int r = 0; r < N_RADIAL; r++) {
        wqr[r] = pack2(Wf[r * F3 + c], Wf[r * F3 + FDIM + c]);
        wm[r]  = Wf[r * F3 + 2 * FDIM + c];
    }
    const float bq = bf[c], bR = bf[FDIM + c], bm = bf[2 * FDIM + c];

    const int beg = g_off[i];
    const int end = g_off[i + 1];

    float aq = 0.0f, a0 = 0.0f, a1 = 0.0f, a2 = 0.0f;

    for (int base = beg; base < end; base += CHUNK) {
        const int m = min(CHUNK, end - base);

        __syncthreads();   // previous chunk fully consumed before overwrite
        if (c < m) {
            const int e = g_perm[base + c];
            sj[c] = g_j[base + c];

            const float ex = ew[3 * e + 0];
            const float ey = ew[3 * e + 1];
            const float ez = ew[3 * e + 2];
            const float dd = fmaf(ex, ex, fmaf(ey, ey, ez * ez));
            const float rd = rsqrtf(dd);
            const float d  = dd * rd;

            float s1, c1;
            __sincosf(d * (PI_F / CUTOFF), &s1, &c1);
            float env = 0.5f * (c1 + 1.0f);
            env = (d < CUTOFF) ? env : 0.0f;

            float* row = srec[c];
            row[0] = ex * rd;
            row[1] = ey * rd;
            row[2] = ez * rd;
            row[3] = env;

            const float re    = rd * env;
            const float two_c = 2.0f * c1;
            float sm1 = 0.0f, sn = s1;
            #pragma unroll
            for (int n = 0; n < N_RADIAL; n++) {
                const float b = sn * re;
                row[4 + 2 * n]     = b;    // duplicated pair for LDS.64 -> fma2
                row[5 + 2 * n]     = b;
                const float nx = two_c * sn - sm1;
                sm1 = sn; sn = nx;
            }
        }
        __syncthreads();

        #pragma unroll 2
        for (int t = 0; t < m; t++) {
            const int j = sj[t];
            const float d0  = srec[t][0];
            const float d1  = srec[t][1];
            const float d2  = srec[t][2];
            const float env = srec[t][3];

            u64   fqr = pack2(bq * env, bR * env);
            float fm  = bm * env;
            #pragma unroll
            for (int r = 0; r < N_RADIAL; r++) {
                const float2 b2v = *(const float2*)&srec[t][4 + 2 * r];  // LDS.64 broadcast
                fma2(fqr, pack2(b2v.x, b2v.y), wqr[r]);
                fm = fmaf(b2v.x, wm[r], fm);
            }
            float fq, fR; unpack2(fqr, fq, fR);

            const float* xr = g_x + (size_t)j * F3;
            const float dq = fq * xr[c];
            const float dR = fR * xr[FDIM + c];
            const float dm = fm * xr[2 * FDIM + c];

            const float* mr = mu + (size_t)j * F3;
            aq += dq;
            a0 = fmaf(dR, d0, fmaf(dm, mr[c],            a0));
            a1 = fmaf(dR, d1, fmaf(dm, mr[FDIM + c],     a1));
            a2 = fmaf(dR, d2, fmaf(dm, mr[2 * FDIM + c], a2));
        }
    }

    qout[(size_t)i * FDIM + c] = q[(size_t)i * FDIM + c] + aq;
    float* mo = muout + (size_t)i * F3;
    const float* mi = mu + (size_t)i * F3;
    mo[c]            = mi[c]            + a0;
    mo[FDIM + c]     = mi[FDIM + c]     + a1;
    mo[2 * FDIM + c] = mi[2 * FDIM + c] + a2;
}

// ---------------------------------------------------------------------------
extern "C" void kernel_launch(void* const* d_in, const int* in_sizes, int n_in,
                              void* d_out, int out_size)
{
    const float* q   = (const float*)d_in[0];
    const float* mu  = (const float*)d_in[1];
    const int*   ei  = (const int*)  d_in[2];
    const float* ew  = (const float*)d_in[3];
    const float* W1  = (const float*)d_in[4];
    const float* b1  = (const float*)d_in[5];
    const float* W2  = (const float*)d_in[6];
    const float* b2  = (const float*)d_in[7];
    const float* Wf  = (const float*)d_in[8];
    const float* bf  = (const float*)d_in[9];

    float* out   = (float*)d_out;
    float* qout  = out;                                   // [N, F]
    float* muout = out + (size_t)N_ATOMS * FDIM;          // [N, 3, F]

    float* fx; cudaGetSymbolAddress((void**)&fx, g_x);

    // CSR build (destination-grouped edge order)
    zero_counts<<<(N_ATOMS + 255) / 256, 256>>>();
    hist_kernel<<<N_EDGES / 256, 256>>>(ei);
    scan_kernel<<<1, 1024>>>();
    scatter_kernel<<<N_EDGES / 256, 256>>>(ei);

    // node MLP -> g_x
    mlp_kernel<<<N_ATOMS / 32, 256>>>(q, W1, b1, W2, b2, fx);

    // fused geometry + filter + pull accumulation, writes final outputs
    node_kernel<<<N_ATOMS, 128>>>(q, mu, ew, Wf, bf, qout, muout);
}